// round 2
// baseline (speedup 1.0000x reference)
#include <cuda_runtime.h>
#include <math.h>

#define NN 100000
#define NE 1600000
#define RR 4
#define DD 128
#define CC 2

// ---- scratch (device globals: no allocation allowed in kernel_launch) ----
__device__ float g_xw[(size_t)RR * NN * DD];   // 204.8 MB  transformed features
__device__ float g_h1[(size_t)NN * DD];        // 51.2 MB   layer-1 aggregate
__device__ float g_h2[(size_t)NN * DD];        // 51.2 MB   layer-2 aggregate
__device__ float g_xw3[(size_t)RR * NN * CC];  // 3.2 MB    layer-3 transformed
__device__ float g_out3[(size_t)NN * CC];      // 0.8 MB    logits accumulator
__device__ int   g_cnt[NN * RR];
__device__ float g_inv[NN * RR];

// ------------------------------------------------------------------ utils
__global__ void zero_f_kernel(float* p, int n) {
    int i = blockIdx.x * blockDim.x + threadIdx.x;
    int stride = gridDim.x * blockDim.x;
    for (; i < n; i += stride) p[i] = 0.0f;
}
__global__ void zero_i_kernel(int* p, int n) {
    int i = blockIdx.x * blockDim.x + threadIdx.x;
    if (i < n) p[i] = 0;
}

// count incoming edges per (dst, relation)
__global__ void count_kernel(const int* __restrict__ ei, const int* __restrict__ et) {
    int e = blockIdx.x * blockDim.x + threadIdx.x;
    if (e < NE) {
        int d = ei[NE + e];
        int t = et[e];
        atomicAdd(&g_cnt[d * RR + t], 1);
    }
}
__global__ void inv_kernel() {
    int i = blockIdx.x * blockDim.x + threadIdx.x;
    if (i < NN * RR) g_inv[i] = 1.0f / fmaxf((float)g_cnt[i], 1.0f);
}

// ------------------------------------------------- transform: XW[r,n,:] = act(X[n,:]) @ W[r]
// block: 256 threads, 64 rows x 128 cols, one relation (blockIdx.y)
// smem: W_r [128x128] (64KB) + X tile [64x128] (32KB) = 96KB dynamic
__global__ void transform_kernel(const float* __restrict__ X, const float* __restrict__ W,
                                 float* __restrict__ XW, int do_tanh) {
    extern __shared__ float sm[];
    float* Ws = sm;              // [128][128]
    float* Xs = sm + DD * DD;    // [64][128]

    const int r  = blockIdx.y;
    const int n0 = blockIdx.x * 64;
    const int t  = threadIdx.x;
    const float* Wr = W + (size_t)r * DD * DD;

    for (int i = t; i < DD * DD; i += 256) Ws[i] = Wr[i];
    for (int i = t; i < 64 * DD; i += 256) {
        int row = i >> 7, col = i & 127;
        int n = n0 + row;
        float v = (n < NN) ? X[(size_t)n * DD + col] : 0.0f;
        Xs[i] = do_tanh ? tanhf(v) : v;
    }
    __syncthreads();

    const int tx = t & 31;   // col group: cols [4*tx, 4*tx+3]
    const int ty = t >> 5;   // row group: rows [8*ty, 8*ty+7]

    float acc[8][4];
#pragma unroll
    for (int i = 0; i < 8; i++)
#pragma unroll
        for (int j = 0; j < 4; j++) acc[i][j] = 0.0f;

    for (int k0 = 0; k0 < DD; k0 += 4) {
        float4 b0 = *reinterpret_cast<const float4*>(&Ws[(k0 + 0) * DD + tx * 4]);
        float4 b1 = *reinterpret_cast<const float4*>(&Ws[(k0 + 1) * DD + tx * 4]);
        float4 b2 = *reinterpret_cast<const float4*>(&Ws[(k0 + 2) * DD + tx * 4]);
        float4 b3 = *reinterpret_cast<const float4*>(&Ws[(k0 + 3) * DD + tx * 4]);
#pragma unroll
        for (int i = 0; i < 8; i++) {
            float4 a = *reinterpret_cast<const float4*>(&Xs[(ty * 8 + i) * DD + k0]);
            acc[i][0] = fmaf(a.x, b0.x, fmaf(a.y, b1.x, fmaf(a.z, b2.x, fmaf(a.w, b3.x, acc[i][0]))));
            acc[i][1] = fmaf(a.x, b0.y, fmaf(a.y, b1.y, fmaf(a.z, b2.y, fmaf(a.w, b3.y, acc[i][1]))));
            acc[i][2] = fmaf(a.x, b0.z, fmaf(a.y, b1.z, fmaf(a.z, b2.z, fmaf(a.w, b3.z, acc[i][2]))));
            acc[i][3] = fmaf(a.x, b0.w, fmaf(a.y, b1.w, fmaf(a.z, b2.w, fmaf(a.w, b3.w, acc[i][3]))));
        }
    }

#pragma unroll
    for (int i = 0; i < 8; i++) {
        int n = n0 + ty * 8 + i;
        if (n < NN) {
            float4 v = make_float4(acc[i][0], acc[i][1], acc[i][2], acc[i][3]);
            *reinterpret_cast<float4*>(&XW[((size_t)r * NN + n) * DD + tx * 4]) = v;
        }
    }
}

// ----------------------------------------------------- scatter: one warp per edge
// out[dst,:] += XW[et, src, :] * inv_cnt[dst, et]   via vector red (L2-resident target)
__global__ void scatter_kernel(const float* __restrict__ XW,
                               const int* __restrict__ ei, const int* __restrict__ et,
                               float* __restrict__ out) {
    int gt = blockIdx.x * blockDim.x + threadIdx.x;
    int w = gt >> 5, lane = gt & 31;
    if (w >= NE) return;

    int s = 0, d = 0, ty = 0;
    float iv = 0.0f;
    if (lane == 0) {
        s = ei[w];
        d = ei[NE + w];
        ty = et[w];
        iv = g_inv[d * RR + ty];
    }
    s  = __shfl_sync(0xffffffffu, s, 0);
    d  = __shfl_sync(0xffffffffu, d, 0);
    ty = __shfl_sync(0xffffffffu, ty, 0);
    iv = __shfl_sync(0xffffffffu, iv, 0);

    float4 v = reinterpret_cast<const float4*>(XW + ((size_t)ty * NN + s) * DD)[lane];
    float* o = out + (size_t)d * DD + lane * 4;
    asm volatile("red.global.add.v4.f32 [%0], {%1, %2, %3, %4};"
                 :: "l"(o), "f"(v.x * iv), "f"(v.y * iv), "f"(v.z * iv), "f"(v.w * iv)
                 : "memory");
}

// ---------------------------------------------- layer 3 transform (out cols = 2)
__global__ void transform3_kernel(const float* __restrict__ H, const float* __restrict__ W3) {
    __shared__ float hs[32 * DD];       // 16KB
    __shared__ float ws[RR * DD * CC];  // 4KB
    const int t  = threadIdx.x;  // 128
    const int n0 = blockIdx.x * 32;

    for (int i = t; i < RR * DD * CC; i += 128) ws[i] = W3[i];
    for (int i = t; i < 32 * DD; i += 128) {
        int row = i >> 7, col = i & 127;
        int n = n0 + row;
        hs[i] = (n < NN) ? tanhf(H[(size_t)n * DD + col]) : 0.0f;
    }
    __syncthreads();

    for (int o = t; o < 32 * RR * CC; o += 128) {
        int node = o >> 3, rc = o & 7;
        int r = rc >> 1, c = rc & 1;
        float acc = 0.0f;
#pragma unroll 8
        for (int k = 0; k < DD; k++)
            acc = fmaf(hs[node * DD + k], ws[(r * DD + k) * CC + c], acc);
        int n = n0 + node;
        if (n < NN) g_xw3[((size_t)r * NN + n) * CC + c] = acc;
    }
}

// layer-3 scatter: one thread per edge (only 2 floats per edge)
__global__ void scatter3_kernel(const int* __restrict__ ei, const int* __restrict__ et) {
    int e = blockIdx.x * blockDim.x + threadIdx.x;
    if (e >= NE) return;
    int s = ei[e], d = ei[NE + e], ty = et[e];
    float iv = g_inv[d * RR + ty];
    float2 v = *reinterpret_cast<const float2*>(&g_xw3[((size_t)ty * NN + s) * CC]);
    float* o = &g_out3[(size_t)d * CC];
    asm volatile("red.global.add.v2.f32 [%0], {%1, %2};"
                 :: "l"(o), "f"(v.x * iv), "f"(v.y * iv) : "memory");
}

// softmax + write outputs: d_out = [softmax(N*C), logits(N*C)]
__global__ void softmax_kernel(float* __restrict__ out, int out_size) {
    int n = blockIdx.x * blockDim.x + threadIdx.x;
    if (n >= NN) return;
    float a = g_out3[n * 2], b = g_out3[n * 2 + 1];
    float m = fmaxf(a, b);
    float ea = __expf(a - m), eb = __expf(b - m);
    float s = 1.0f / (ea + eb);
    out[n * 2]     = ea * s;
    out[n * 2 + 1] = eb * s;
    if (out_size >= 2 * NN * CC) {
        out[NN * CC + n * 2]     = a;
        out[NN * CC + n * 2 + 1] = b;
    }
}

// ------------------------------------------------------------------ launch
extern "C" void kernel_launch(void* const* d_in, const int* in_sizes, int n_in,
                              void* d_out, int out_size) {
    const float* x  = (const float*)d_in[0];
    const int*   ei = (const int*)d_in[1];
    const int*   et = (const int*)d_in[2];
    const float* W1 = (const float*)d_in[3];
    const float* W2 = (const float*)d_in[4];
    const float* W3 = (const float*)d_in[5];
    float* out = (float*)d_out;

    static int smem_set = 0;
    if (!smem_set) {
        cudaFuncSetAttribute(transform_kernel,
                             cudaFuncAttributeMaxDynamicSharedMemorySize, 98304);
        smem_set = 1;
    }

    float *p_xw, *p_h1, *p_h2, *p_out3;
    int* p_cnt;
    cudaGetSymbolAddress((void**)&p_xw, g_xw);
    cudaGetSymbolAddress((void**)&p_h1, g_h1);
    cudaGetSymbolAddress((void**)&p_h2, g_h2);
    cudaGetSymbolAddress((void**)&p_out3, g_out3);
    cudaGetSymbolAddress((void**)&p_cnt, g_cnt);

    const int smem = 98304;
    dim3 tgrid((NN + 63) / 64, RR);

    // counts -> inverse means
    zero_i_kernel<<<(NN * RR + 255) / 256, 256>>>(p_cnt, NN * RR);
    count_kernel<<<(NE + 255) / 256, 256>>>(ei, et);
    inv_kernel<<<(NN * RR + 255) / 256, 256>>>();

    // layer 1
    transform_kernel<<<tgrid, 256, smem>>>(x, W1, p_xw, 0);
    zero_f_kernel<<<8192, 256>>>(p_h1, NN * DD);
    scatter_kernel<<<(NE * 32 + 255) / 256, 256>>>(p_xw, ei, et, p_h1);

    // layer 2
    transform_kernel<<<tgrid, 256, smem>>>(p_h1, W2, p_xw, 1);
    zero_f_kernel<<<8192, 256>>>(p_h2, NN * DD);
    scatter_kernel<<<(NE * 32 + 255) / 256, 256>>>(p_xw, ei, et, p_h2);

    // layer 3
    transform3_kernel<<<(NN + 31) / 32, 128>>>(p_h2, W3);
    zero_f_kernel<<<(NN * CC + 255) / 256, 256>>>(p_out3, NN * CC);
    scatter3_kernel<<<(NE + 255) / 256, 256>>>(ei, et);

    softmax_kernel<<<(NN + 255) / 256, 256>>>(out, out_size);
}

// round 5
// speedup vs baseline: 1.2687x; 1.2687x over previous
#include <cuda_runtime.h>
#include <cuda_bf16.h>
#include <math.h>
#include <cstdint>

#define NN 100000
#define NE 1600000
#define RR 4
#define DD 128
#define CC 2

// ---- scratch (device globals: no allocation allowed in kernel_launch) ----
__device__ float g_xw[(size_t)RR * NN * DD];   // 204.8 MB  transformed features
__device__ float g_h1[(size_t)NN * DD];        // 51.2 MB   layer-1 aggregate
__device__ float g_h2[(size_t)NN * DD];        // 51.2 MB   layer-2 aggregate
__device__ float g_xw3[(size_t)RR * NN * CC];  // 3.2 MB    layer-3 transformed
__device__ float g_out3[(size_t)NN * CC];      // 0.8 MB    logits accumulator
__device__ int   g_cnt[NN * RR];
__device__ float g_inv[NN * RR];
// bf16 split buffers
__device__ __nv_bfloat16 g_xhi[(size_t)NN * DD];          // 25.6 MB
__device__ __nv_bfloat16 g_xlo[(size_t)NN * DD];          // 25.6 MB
__device__ __nv_bfloat16 g_whi[2 * RR * DD * DD];         // W1,W2 transposed hi
__device__ __nv_bfloat16 g_wlo[2 * RR * DD * DD];         // W1,W2 transposed lo

__device__ __forceinline__ uint32_t smem_u32(const void* p) {
    uint32_t a;
    asm("{ .reg .u64 t; cvta.to.shared.u64 t, %1; cvt.u32.u64 %0, t; }" : "=r"(a) : "l"(p));
    return a;
}

// ------------------------------------------------------------------ utils
__global__ void zero_f_kernel(float* p, int n) {
    int i = blockIdx.x * blockDim.x + threadIdx.x;
    int stride = gridDim.x * blockDim.x;
    for (; i < n; i += stride) p[i] = 0.0f;
}
__global__ void zero_i_kernel(int* p, int n) {
    int i = blockIdx.x * blockDim.x + threadIdx.x;
    if (i < n) p[i] = 0;
}
__global__ void count_kernel(const int* __restrict__ ei, const int* __restrict__ et) {
    int e = blockIdx.x * blockDim.x + threadIdx.x;
    if (e < NE) atomicAdd(&g_cnt[ei[NE + e] * RR + et[e]], 1);
}
__global__ void inv_kernel() {
    int i = blockIdx.x * blockDim.x + threadIdx.x;
    if (i < NN * RR) g_inv[i] = 1.0f / fmaxf((float)g_cnt[i], 1.0f);
}

// ---------------------------------------------- bf16 split conversions
__global__ void convert_x_kernel(const float* __restrict__ in, int do_tanh) {
    int i = blockIdx.x * blockDim.x + threadIdx.x;
    if (i >= NN * DD) return;
    float v = in[i];
    if (do_tanh) v = tanhf(v);
    __nv_bfloat16 hi = __float2bfloat16_rn(v);
    __nv_bfloat16 lo = __float2bfloat16_rn(v - __bfloat162float(hi));
    g_xhi[i] = hi;
    g_xlo[i] = lo;
}
// W [R,K,N] fp32 -> transposed bf16 splits at [layer][r][n][k]
__global__ void convert_w_kernel(const float* __restrict__ W, int layer) {
    int i = blockIdx.x * blockDim.x + threadIdx.x;
    if (i >= RR * DD * DD) return;
    int r = i / (DD * DD), rem = i % (DD * DD);
    int n = rem / DD, k = rem % DD;
    float v = W[(r * DD + k) * DD + n];
    __nv_bfloat16 hi = __float2bfloat16_rn(v);
    __nv_bfloat16 lo = __float2bfloat16_rn(v - __bfloat162float(hi));
    g_whi[layer * RR * DD * DD + i] = hi;
    g_wlo[layer * RR * DD * DD + i] = lo;
}

// ------------------------------------------- HMMA transform: XW[r] = X @ W_r
// mma.sync m16n8k16 bf16, 3-product split. 128x128 tile per CTA, 8 warps (64x32 each).
// smem: padded [128][136] bf16 tiles: Ahi | Alo | Bhi | Blo  (4 * 34816 = 139264 B)
#define TPAD 136                       // bf16 elements per padded row
#define TBYTES (128 * TPAD * 2)        // 34816

__global__ void __launch_bounds__(256, 1) mma_transform_kernel(int layer, float* __restrict__ XW) {
    extern __shared__ char smem[];
    const uint32_t sbase = smem_u32(smem);
    const int tid = threadIdx.x;
    const int wid = tid >> 5, lane = tid & 31;
    const int r = blockIdx.x & 3;
    const int n0 = (blockIdx.x >> 2) * 128;

    const uint32_t A_HI = 0, A_LO = TBYTES, B_HI = 2 * TBYTES, B_LO = 3 * TBYTES;

    // ---- load tiles (128 rows x 16 chunks of 8 bf16) ----
    const __nv_bfloat16* wh = g_whi + ((size_t)layer * RR + r) * DD * DD;
    const __nv_bfloat16* wl = g_wlo + ((size_t)layer * RR + r) * DD * DD;
    for (int u = tid; u < 2048; u += 256) {
        int row = u >> 4;
        int col = (u & 15) * 8;
        uint32_t off = (uint32_t)(row * (TPAD * 2) + col * 2);
        uint4 vh = make_uint4(0, 0, 0, 0), vl = make_uint4(0, 0, 0, 0);
        int n = n0 + row;
        if (n < NN) {
            vh = *reinterpret_cast<const uint4*>(g_xhi + (size_t)n * DD + col);
            vl = *reinterpret_cast<const uint4*>(g_xlo + (size_t)n * DD + col);
        }
        *reinterpret_cast<uint4*>(smem + A_HI + off) = vh;
        *reinterpret_cast<uint4*>(smem + A_LO + off) = vl;
        *reinterpret_cast<uint4*>(smem + B_HI + off) =
            *reinterpret_cast<const uint4*>(wh + (size_t)row * DD + col);
        *reinterpret_cast<uint4*>(smem + B_LO + off) =
            *reinterpret_cast<const uint4*>(wl + (size_t)row * DD + col);
    }
    __syncthreads();

    // warp tile: 64 rows x 32 cols
    const int wm = (wid & 1) * 64;     // warp m offset
    const int wn = (wid >> 1) * 32;    // warp n offset

    float acc[4][4][4];
#pragma unroll
    for (int mi = 0; mi < 4; mi++)
#pragma unroll
        for (int ni = 0; ni < 4; ni++)
#pragma unroll
            for (int q = 0; q < 4; q++) acc[mi][ni][q] = 0.0f;

    // ldmatrix lane addressing (byte offsets within a tile)
    const int a_row = (lane & 15);            // + (lane>>4)*8 cols
    const int a_kof = (lane >> 4) * 8;
    const int b_row = ((lane >> 4) << 3) + (lane & 7);   // n row within 16
    const int b_kof = ((lane >> 3) & 1) * 8;

#pragma unroll
    for (int pass = 0; pass < 3; pass++) {
        const uint32_t aB = sbase + ((pass == 2) ? A_LO : A_HI);
        const uint32_t bB = sbase + ((pass == 1) ? B_LO : B_HI);
#pragma unroll
        for (int ks = 0; ks < 8; ks++) {
            const int k0 = ks * 16;
            uint32_t a[4][4];
#pragma unroll
            for (int mi = 0; mi < 4; mi++) {
                uint32_t addr = aB + (uint32_t)((wm + mi * 16 + a_row) * (TPAD * 2) +
                                                (k0 + a_kof) * 2);
                asm volatile("ldmatrix.sync.aligned.m8n8.x4.shared.b16 {%0,%1,%2,%3}, [%4];"
                             : "=r"(a[mi][0]), "=r"(a[mi][1]), "=r"(a[mi][2]), "=r"(a[mi][3])
                             : "r"(addr));
            }
            uint32_t b[2][4];
#pragma unroll
            for (int nb = 0; nb < 2; nb++) {
                uint32_t addr = bB + (uint32_t)((wn + nb * 16 + b_row) * (TPAD * 2) +
                                                (k0 + b_kof) * 2);
                asm volatile("ldmatrix.sync.aligned.m8n8.x4.shared.b16 {%0,%1,%2,%3}, [%4];"
                             : "=r"(b[nb][0]), "=r"(b[nb][1]), "=r"(b[nb][2]), "=r"(b[nb][3])
                             : "r"(addr));
            }
#pragma unroll
            for (int mi = 0; mi < 4; mi++) {
#pragma unroll
                for (int ni = 0; ni < 4; ni++) {
                    uint32_t b0 = b[ni >> 1][(ni & 1) ? 2 : 0];
                    uint32_t b1 = b[ni >> 1][(ni & 1) ? 3 : 1];
                    asm volatile(
                        "mma.sync.aligned.m16n8k16.row.col.f32.bf16.bf16.f32 "
                        "{%0,%1,%2,%3}, {%4,%5,%6,%7}, {%8,%9}, {%0,%1,%2,%3};"
                        : "+f"(acc[mi][ni][0]), "+f"(acc[mi][ni][1]),
                          "+f"(acc[mi][ni][2]), "+f"(acc[mi][ni][3])
                        : "r"(a[mi][0]), "r"(a[mi][1]), "r"(a[mi][2]), "r"(a[mi][3]),
                          "r"(b0), "r"(b1));
                }
            }
        }
    }

    // ---- epilogue: write fp32 to XW[r][n][:] ----
    const int gid = lane >> 2, tq = lane & 3;
    float* base_out = XW + (size_t)r * NN * DD;
#pragma unroll
    for (int mi = 0; mi < 4; mi++) {
        int row0 = n0 + wm + mi * 16 + gid;
        int row1 = row0 + 8;
#pragma unroll
        for (int ni = 0; ni < 4; ni++) {
            int col = wn + ni * 8 + tq * 2;
            if (row0 < NN)
                *reinterpret_cast<float2*>(base_out + (size_t)row0 * DD + col) =
                    make_float2(acc[mi][ni][0], acc[mi][ni][1]);
            if (row1 < NN)
                *reinterpret_cast<float2*>(base_out + (size_t)row1 * DD + col) =
                    make_float2(acc[mi][ni][2], acc[mi][ni][3]);
        }
    }
}

// ----------------------------------------------------- scatter: one warp per edge
__global__ void scatter_kernel(const float* __restrict__ XW,
                               const int* __restrict__ ei, const int* __restrict__ et,
                               float* __restrict__ out) {
    int gt = blockIdx.x * blockDim.x + threadIdx.x;
    int w = gt >> 5, lane = gt & 31;
    if (w >= NE) return;

    int s = 0, d = 0, ty = 0;
    float iv = 0.0f;
    if (lane == 0) {
        s = ei[w];
        d = ei[NE + w];
        ty = et[w];
        iv = g_inv[d * RR + ty];
    }
    s  = __shfl_sync(0xffffffffu, s, 0);
    d  = __shfl_sync(0xffffffffu, d, 0);
    ty = __shfl_sync(0xffffffffu, ty, 0);
    iv = __shfl_sync(0xffffffffu, iv, 0);

    float4 v = reinterpret_cast<const float4*>(XW + ((size_t)ty * NN + s) * DD)[lane];
    float* o = out + (size_t)d * DD + lane * 4;
    asm volatile("red.global.add.v4.f32 [%0], {%1, %2, %3, %4};"
                 :: "l"(o), "f"(v.x * iv), "f"(v.y * iv), "f"(v.z * iv), "f"(v.w * iv)
                 : "memory");
}

// ---------------------------------------------- layer 3 transform (out cols = 2)
__global__ void transform3_kernel(const float* __restrict__ H, const float* __restrict__ W3) {
    __shared__ float hs[32 * DD];
    __shared__ float ws[RR * DD * CC];
    const int t  = threadIdx.x;  // 128
    const int n0 = blockIdx.x * 32;

    for (int i = t; i < RR * DD * CC; i += 128) ws[i] = W3[i];
    for (int i = t; i < 32 * DD; i += 128) {
        int row = i >> 7, col = i & 127;
        int n = n0 + row;
        hs[i] = (n < NN) ? tanhf(H[(size_t)n * DD + col]) : 0.0f;
    }
    __syncthreads();

    for (int o = t; o < 32 * RR * CC; o += 128) {
        int node = o >> 3, rc = o & 7;
        int r = rc >> 1, c = rc & 1;
        float acc = 0.0f;
#pragma unroll 8
        for (int k = 0; k < DD; k++)
            acc = fmaf(hs[node * DD + k], ws[(r * DD + k) * CC + c], acc);
        int n = n0 + node;
        if (n < NN) g_xw3[((size_t)r * NN + n) * CC + c] = acc;
    }
}

__global__ void scatter3_kernel(const int* __restrict__ ei, const int* __restrict__ et) {
    int e = blockIdx.x * blockDim.x + threadIdx.x;
    if (e >= NE) return;
    int s = ei[e], d = ei[NE + e], ty = et[e];
    float iv = g_inv[d * RR + ty];
    float2 v = *reinterpret_cast<const float2*>(&g_xw3[((size_t)ty * NN + s) * CC]);
    float* o = &g_out3[(size_t)d * CC];
    asm volatile("red.global.add.v2.f32 [%0], {%1, %2};"
                 :: "l"(o), "f"(v.x * iv), "f"(v.y * iv) : "memory");
}

__global__ void softmax_kernel(float* __restrict__ out, int out_size) {
    int n = blockIdx.x * blockDim.x + threadIdx.x;
    if (n >= NN) return;
    float a = g_out3[n * 2], b = g_out3[n * 2 + 1];
    float m = fmaxf(a, b);
    float ea = __expf(a - m), eb = __expf(b - m);
    float s = 1.0f / (ea + eb);
    out[n * 2]     = ea * s;
    out[n * 2 + 1] = eb * s;
    if (out_size >= 2 * NN * CC) {
        out[NN * CC + n * 2]     = a;
        out[NN * CC + n * 2 + 1] = b;
    }
}

// ------------------------------------------------------------------ launch
extern "C" void kernel_launch(void* const* d_in, const int* in_sizes, int n_in,
                              void* d_out, int out_size) {
    const float* x  = (const float*)d_in[0];
    const int*   ei = (const int*)d_in[1];
    const int*   et = (const int*)d_in[2];
    const float* W1 = (const float*)d_in[3];
    const float* W2 = (const float*)d_in[4];
    const float* W3 = (const float*)d_in[5];
    float* out = (float*)d_out;

    static int attr_set = 0;
    if (!attr_set) {
        cudaFuncSetAttribute(mma_transform_kernel,
                             cudaFuncAttributeMaxDynamicSharedMemorySize, 4 * TBYTES);
        attr_set = 1;
    }

    float *p_xw, *p_h1, *p_h2, *p_out3;
    int* p_cnt;
    cudaGetSymbolAddress((void**)&p_xw, g_xw);
    cudaGetSymbolAddress((void**)&p_h1, g_h1);
    cudaGetSymbolAddress((void**)&p_h2, g_h2);
    cudaGetSymbolAddress((void**)&p_out3, g_out3);
    cudaGetSymbolAddress((void**)&p_cnt, g_cnt);

    const int mma_smem = 4 * TBYTES;                 // 139264
    const int mma_grid = ((NN + 127) / 128) * RR;    // 782 * 4 = 3128

    // counts -> inverse means
    zero_i_kernel<<<(NN * RR + 255) / 256, 256>>>(p_cnt, NN * RR);
    count_kernel<<<(NE + 255) / 256, 256>>>(ei, et);
    inv_kernel<<<(NN * RR + 255) / 256, 256>>>();

    // weight splits (tiny)
    convert_w_kernel<<<(RR * DD * DD + 255) / 256, 256>>>(W1, 0);
    convert_w_kernel<<<(RR * DD * DD + 255) / 256, 256>>>(W2, 1);

    // layer 1
    convert_x_kernel<<<(NN * DD + 255) / 256, 256>>>(x, 0);
    mma_transform_kernel<<<mma_grid, 256, mma_smem>>>(0, p_xw);
    zero_f_kernel<<<8192, 256>>>(p_h1, NN * DD);
    scatter_kernel<<<(NE * 32 + 255) / 256, 256>>>(p_xw, ei, et, p_h1);

    // layer 2
    convert_x_kernel<<<(NN * DD + 255) / 256, 256>>>(p_h1, 1);
    mma_transform_kernel<<<mma_grid, 256, mma_smem>>>(1, p_xw);
    zero_f_kernel<<<8192, 256>>>(p_h2, NN * DD);
    scatter_kernel<<<(NE * 32 + 255) / 256, 256>>>(p_xw, ei, et, p_h2);

    // layer 3
    transform3_kernel<<<(NN + 31) / 32, 128>>>(p_h2, W3);
    zero_f_kernel<<<(NN * CC + 255) / 256, 256>>>(p_out3, NN * CC);
    scatter3_kernel<<<(NE + 255) / 256, 256>>>(ei, et);

    softmax_kernel<<<(NN + 255) / 256, 256>>>(out, out_size);
}

// round 6
// speedup vs baseline: 2.1472x; 1.6925x over previous
#include <cuda_runtime.h>
#include <cuda_bf16.h>
#include <math.h>
#include <cstdint>

#define NN 100000
#define NE 1600000
#define RR 4
#define DD 128
#define CC 2
#define NR (NN * RR)                 // 400000 segments
#define SCAN_NBLK ((NR + 1023) / 1024)   // 391

// ---- scratch (device globals: no allocation allowed in kernel_launch) ----
__device__ float g_h1[(size_t)NN * DD];        // 51.2 MB  layer-1 out (tanh)
__device__ float g_h2[(size_t)NN * DD];        // 51.2 MB  layer-2 out (tanh)
__device__ float g_xw3[(size_t)RR * NN * CC];  // 3.2 MB   layer-3 transformed
__device__ float g_out3[(size_t)NN * CC];      // 0.8 MB   logits accumulator
__device__ int   g_cnt[NR];
__device__ float g_inv[NR];
// CSR (edges sorted by (dst, relation))
__device__ int   g_off[NR + 1];
__device__ int   g_cur[NR];
__device__ int   g_bsum[512];
__device__ int   g_boff[512];
__device__ unsigned g_csr[NE];                 // src per edge, segment-ordered
// aggregated means, pre-split bf16 hi/lo: layout [n][r][128]
__device__ __nv_bfloat16 g_ahi[(size_t)NN * RR * DD];   // 102.4 MB
__device__ __nv_bfloat16 g_alo[(size_t)NN * RR * DD];   // 102.4 MB
// W1,W2 transposed bf16 splits: [layer][r][n_out][k]
__device__ __nv_bfloat16 g_whi[2 * RR * DD * DD];
__device__ __nv_bfloat16 g_wlo[2 * RR * DD * DD];

__device__ __forceinline__ uint32_t smem_u32(const void* p) {
    uint32_t a;
    asm("{ .reg .u64 t; cvta.to.shared.u64 t, %1; cvt.u32.u64 %0, t; }" : "=r"(a) : "l"(p));
    return a;
}

// ------------------------------------------------------------------ utils
__global__ void zero_f_kernel(float* p, int n) {
    int i = blockIdx.x * blockDim.x + threadIdx.x;
    int stride = gridDim.x * blockDim.x;
    for (; i < n; i += stride) p[i] = 0.0f;
}
__global__ void zero_i_kernel(int* p, int n) {
    int i = blockIdx.x * blockDim.x + threadIdx.x;
    if (i < n) p[i] = 0;
}
__global__ void count_kernel(const int* __restrict__ ei, const int* __restrict__ et) {
    int e = blockIdx.x * blockDim.x + threadIdx.x;
    if (e < NE) atomicAdd(&g_cnt[ei[NE + e] * RR + et[e]], 1);
}
__global__ void inv_kernel() {
    int i = blockIdx.x * blockDim.x + threadIdx.x;
    if (i < NR) g_inv[i] = 1.0f / fmaxf((float)g_cnt[i], 1.0f);
}

// ---------------------------------------------- CSR build: scan + placement
__global__ void k_blocksum() {
    __shared__ int sh[256];
    int b = blockIdx.x, t = threadIdx.x;
    int base = b * 1024 + t * 4;
    int s = 0;
#pragma unroll
    for (int j = 0; j < 4; j++) {
        int idx = base + j;
        if (idx < NR) s += g_cnt[idx];
    }
    sh[t] = s;
    __syncthreads();
    for (int o = 128; o > 0; o >>= 1) {
        if (t < o) sh[t] += sh[t + o];
        __syncthreads();
    }
    if (t == 0) g_bsum[b] = sh[0];
}
__global__ void k_scanb(int nb) {
    if (threadIdx.x == 0) {
        int run = 0;
        for (int i = 0; i < nb; i++) { g_boff[i] = run; run += g_bsum[i]; }
        g_off[NR] = run;   // == NE
    }
}
__global__ void k_scanlocal() {
    __shared__ int sh[256];
    int b = blockIdx.x, t = threadIdx.x;
    int base = b * 1024 + t * 4;
    int c[4], s = 0;
#pragma unroll
    for (int j = 0; j < 4; j++) {
        int idx = base + j;
        c[j] = (idx < NR) ? g_cnt[idx] : 0;
        s += c[j];
    }
    sh[t] = s;
    __syncthreads();
    for (int o = 1; o < 256; o <<= 1) {
        int u = (t >= o) ? sh[t - o] : 0;
        __syncthreads();
        sh[t] += u;
        __syncthreads();
    }
    int run = g_boff[b] + sh[t] - s;   // exclusive prefix for this thread
#pragma unroll
    for (int j = 0; j < 4; j++) {
        int idx = base + j;
        if (idx < NR) { g_off[idx] = run; run += c[j]; }
    }
}
__global__ void place_kernel(const int* __restrict__ ei, const int* __restrict__ et) {
    int e = blockIdx.x * blockDim.x + threadIdx.x;
    if (e >= NE) return;
    int src = ei[e], d = ei[NE + e], r = et[e];
    int seg = d * RR + r;
    int pos = g_off[seg] + atomicAdd(&g_cur[seg], 1);
    g_csr[pos] = (unsigned)src;
}

// W [R,K,N] fp32 -> transposed bf16 splits at [layer][r][n][k]
__global__ void convert_w_kernel(const float* __restrict__ W, int layer) {
    int i = blockIdx.x * blockDim.x + threadIdx.x;
    if (i >= RR * DD * DD) return;
    int r = i / (DD * DD), rem = i % (DD * DD);
    int n = rem / DD, k = rem % DD;
    float v = W[(r * DD + k) * DD + n];
    __nv_bfloat16 hi = __float2bfloat16_rn(v);
    __nv_bfloat16 lo = __float2bfloat16_rn(v - __bfloat162float(hi));
    g_whi[layer * RR * DD * DD + i] = hi;
    g_wlo[layer * RR * DD * DD + i] = lo;
}

// ------------------------------------- gather-mean per (dst, relation), atomic-free
// one warp per dst node; A[dst][r][:] = inv * sum(x[src]); split to bf16 hi/lo
__global__ void __launch_bounds__(256) gather_kernel(const float* __restrict__ X) {
    int gw = (blockIdx.x * blockDim.x + threadIdx.x) >> 5;
    int lane = threadIdx.x & 31;
    if (gw >= NN) return;
    const float4* x4 = reinterpret_cast<const float4*>(X);

#pragma unroll
    for (int r = 0; r < RR; r++) {
        int seg = gw * RR + r;
        int s = g_off[seg], e = g_off[seg + 1];
        float4 acc = make_float4(0.f, 0.f, 0.f, 0.f);
        for (int i = s; i < e; i++) {
            unsigned src = g_csr[i];
            float4 v = x4[(size_t)src * 32 + lane];
            acc.x += v.x; acc.y += v.y; acc.z += v.z; acc.w += v.w;
        }
        float iv = g_inv[seg];
        acc.x *= iv; acc.y *= iv; acc.z *= iv; acc.w *= iv;

        __nv_bfloat16 h0 = __float2bfloat16_rn(acc.x);
        __nv_bfloat16 h1 = __float2bfloat16_rn(acc.y);
        __nv_bfloat16 h2 = __float2bfloat16_rn(acc.z);
        __nv_bfloat16 h3 = __float2bfloat16_rn(acc.w);
        __nv_bfloat16 l0 = __float2bfloat16_rn(acc.x - __bfloat162float(h0));
        __nv_bfloat16 l1 = __float2bfloat16_rn(acc.y - __bfloat162float(h1));
        __nv_bfloat16 l2 = __float2bfloat16_rn(acc.z - __bfloat162float(h2));
        __nv_bfloat16 l3 = __float2bfloat16_rn(acc.w - __bfloat162float(h3));
        uint2 hp, lp;
        hp.x = ((uint32_t)__bfloat16_as_ushort(h1) << 16) | __bfloat16_as_ushort(h0);
        hp.y = ((uint32_t)__bfloat16_as_ushort(h3) << 16) | __bfloat16_as_ushort(h2);
        lp.x = ((uint32_t)__bfloat16_as_ushort(l1) << 16) | __bfloat16_as_ushort(l0);
        lp.y = ((uint32_t)__bfloat16_as_ushort(l3) << 16) | __bfloat16_as_ushort(l2);
        size_t base = (size_t)seg * DD + lane * 4;
        *reinterpret_cast<uint2*>(g_ahi + base) = hp;
        *reinterpret_cast<uint2*>(g_alo + base) = lp;
    }
}

// ------------------------------------------- fused GEMM: h = tanh(sum_r A_r @ W_r)
// 128x128 tile per CTA; loop over relations with register accumulation.
// smem: padded [128][136] bf16 tiles: Ahi | Alo | Bhi | Blo (reloaded per relation)
#define TPAD 136
#define TBYTES (128 * TPAD * 2)        // 34816

__global__ void __launch_bounds__(256, 1) gemm_kernel(int layer, float* __restrict__ OUT) {
    extern __shared__ char smem[];
    const uint32_t sbase = smem_u32(smem);
    const int tid = threadIdx.x;
    const int wid = tid >> 5, lane = tid & 31;
    const int n0 = blockIdx.x * 128;

    const uint32_t A_HI = 0, A_LO = TBYTES, B_HI = 2 * TBYTES, B_LO = 3 * TBYTES;

    const int wm = (wid & 1) * 64;
    const int wn = (wid >> 1) * 32;

    float acc[4][4][4];
#pragma unroll
    for (int mi = 0; mi < 4; mi++)
#pragma unroll
        for (int ni = 0; ni < 4; ni++)
#pragma unroll
            for (int q = 0; q < 4; q++) acc[mi][ni][q] = 0.0f;

    const int a_row = (lane & 15);
    const int a_kof = (lane >> 4) * 8;
    const int b_row = ((lane >> 4) << 3) + (lane & 7);
    const int b_kof = ((lane >> 3) & 1) * 8;

    for (int r = 0; r < RR; r++) {
        __syncthreads();   // protect previous iteration's smem reads
        // ---- load tiles ----
        const __nv_bfloat16* wh = g_whi + ((size_t)layer * RR + r) * DD * DD;
        const __nv_bfloat16* wl = g_wlo + ((size_t)layer * RR + r) * DD * DD;
        for (int u = tid; u < 2048; u += 256) {
            int row = u >> 4;
            int col = (u & 15) * 8;
            uint32_t off = (uint32_t)(row * (TPAD * 2) + col * 2);
            uint4 vh = make_uint4(0, 0, 0, 0), vl = make_uint4(0, 0, 0, 0);
            int n = n0 + row;
            if (n < NN) {
                size_t ab = ((size_t)n * RR + r) * DD + col;
                vh = *reinterpret_cast<const uint4*>(g_ahi + ab);
                vl = *reinterpret_cast<const uint4*>(g_alo + ab);
            }
            *reinterpret_cast<uint4*>(smem + A_HI + off) = vh;
            *reinterpret_cast<uint4*>(smem + A_LO + off) = vl;
            *reinterpret_cast<uint4*>(smem + B_HI + off) =
                *reinterpret_cast<const uint4*>(wh + (size_t)row * DD + col);
            *reinterpret_cast<uint4*>(smem + B_LO + off) =
                *reinterpret_cast<const uint4*>(wl + (size_t)row * DD + col);
        }
        __syncthreads();

        // ---- 3-product split MMA ----
#pragma unroll
        for (int pass = 0; pass < 3; pass++) {
            const uint32_t aB = sbase + ((pass == 2) ? A_LO : A_HI);
            const uint32_t bB = sbase + ((pass == 1) ? B_LO : B_HI);
#pragma unroll
            for (int ks = 0; ks < 8; ks++) {
                const int k0 = ks * 16;
                uint32_t a[4][4];
#pragma unroll
                for (int mi = 0; mi < 4; mi++) {
                    uint32_t addr = aB + (uint32_t)((wm + mi * 16 + a_row) * (TPAD * 2) +
                                                    (k0 + a_kof) * 2);
                    asm volatile("ldmatrix.sync.aligned.m8n8.x4.shared.b16 {%0,%1,%2,%3}, [%4];"
                                 : "=r"(a[mi][0]), "=r"(a[mi][1]), "=r"(a[mi][2]), "=r"(a[mi][3])
                                 : "r"(addr));
                }
                uint32_t b[2][4];
#pragma unroll
                for (int nb = 0; nb < 2; nb++) {
                    uint32_t addr = bB + (uint32_t)((wn + nb * 16 + b_row) * (TPAD * 2) +
                                                    (k0 + b_kof) * 2);
                    asm volatile("ldmatrix.sync.aligned.m8n8.x4.shared.b16 {%0,%1,%2,%3}, [%4];"
                                 : "=r"(b[nb][0]), "=r"(b[nb][1]), "=r"(b[nb][2]), "=r"(b[nb][3])
                                 : "r"(addr));
                }
#pragma unroll
                for (int mi = 0; mi < 4; mi++) {
#pragma unroll
                    for (int ni = 0; ni < 4; ni++) {
                        uint32_t b0 = b[ni >> 1][(ni & 1) ? 2 : 0];
                        uint32_t b1 = b[ni >> 1][(ni & 1) ? 3 : 1];
                        asm volatile(
                            "mma.sync.aligned.m16n8k16.row.col.f32.bf16.bf16.f32 "
                            "{%0,%1,%2,%3}, {%4,%5,%6,%7}, {%8,%9}, {%0,%1,%2,%3};"
                            : "+f"(acc[mi][ni][0]), "+f"(acc[mi][ni][1]),
                              "+f"(acc[mi][ni][2]), "+f"(acc[mi][ni][3])
                            : "r"(a[mi][0]), "r"(a[mi][1]), "r"(a[mi][2]), "r"(a[mi][3]),
                              "r"(b0), "r"(b1));
                    }
                }
            }
        }
    }

    // ---- epilogue: tanh + write fp32 ----
    const int gid = lane >> 2, tq = lane & 3;
#pragma unroll
    for (int mi = 0; mi < 4; mi++) {
        int row0 = n0 + wm + mi * 16 + gid;
        int row1 = row0 + 8;
#pragma unroll
        for (int ni = 0; ni < 4; ni++) {
            int col = wn + ni * 8 + tq * 2;
            if (row0 < NN)
                *reinterpret_cast<float2*>(OUT + (size_t)row0 * DD + col) =
                    make_float2(tanhf(acc[mi][ni][0]), tanhf(acc[mi][ni][1]));
            if (row1 < NN)
                *reinterpret_cast<float2*>(OUT + (size_t)row1 * DD + col) =
                    make_float2(tanhf(acc[mi][ni][2]), tanhf(acc[mi][ni][3]));
        }
    }
}

// ---------------------------------------------- layer 3 (input already tanh'd)
__global__ void transform3_kernel(const float* __restrict__ H, const float* __restrict__ W3) {
    __shared__ float hs[32 * DD];
    __shared__ float ws[RR * DD * CC];
    const int t  = threadIdx.x;  // 128
    const int n0 = blockIdx.x * 32;

    for (int i = t; i < RR * DD * CC; i += 128) ws[i] = W3[i];
    for (int i = t; i < 32 * DD; i += 128) {
        int row = i >> 7, col = i & 127;
        int n = n0 + row;
        hs[i] = (n < NN) ? H[(size_t)n * DD + col] : 0.0f;
    }
    __syncthreads();

    for (int o = t; o < 32 * RR * CC; o += 128) {
        int node = o >> 3, rc = o & 7;
        int r = rc >> 1, c = rc & 1;
        float acc = 0.0f;
#pragma unroll 8
        for (int k = 0; k < DD; k++)
            acc = fmaf(hs[node * DD + k], ws[(r * DD + k) * CC + c], acc);
        int n = n0 + node;
        if (n < NN) g_xw3[((size_t)r * NN + n) * CC + c] = acc;
    }
}

__global__ void scatter3_kernel(const int* __restrict__ ei, const int* __restrict__ et) {
    int e = blockIdx.x * blockDim.x + threadIdx.x;
    if (e >= NE) return;
    int s = ei[e], d = ei[NE + e], ty = et[e];
    float iv = g_inv[d * RR + ty];
    float2 v = *reinterpret_cast<const float2*>(&g_xw3[((size_t)ty * NN + s) * CC]);
    float* o = &g_out3[(size_t)d * CC];
    asm volatile("red.global.add.v2.f32 [%0], {%1, %2};"
                 :: "l"(o), "f"(v.x * iv), "f"(v.y * iv) : "memory");
}

__global__ void softmax_kernel(float* __restrict__ out, int out_size) {
    int n = blockIdx.x * blockDim.x + threadIdx.x;
    if (n >= NN) return;
    float a = g_out3[n * 2], b = g_out3[n * 2 + 1];
    float m = fmaxf(a, b);
    float ea = __expf(a - m), eb = __expf(b - m);
    float s = 1.0f / (ea + eb);
    out[n * 2]     = ea * s;
    out[n * 2 + 1] = eb * s;
    if (out_size >= 2 * NN * CC) {
        out[NN * CC + n * 2]     = a;
        out[NN * CC + n * 2 + 1] = b;
    }
}

// ------------------------------------------------------------------ launch
extern "C" void kernel_launch(void* const* d_in, const int* in_sizes, int n_in,
                              void* d_out, int out_size) {
    const float* x  = (const float*)d_in[0];
    const int*   ei = (const int*)d_in[1];
    const int*   et = (const int*)d_in[2];
    const float* W1 = (const float*)d_in[3];
    const float* W2 = (const float*)d_in[4];
    const float* W3 = (const float*)d_in[5];
    float* out = (float*)d_out;

    static int attr_set = 0;
    if (!attr_set) {
        cudaFuncSetAttribute(gemm_kernel,
                             cudaFuncAttributeMaxDynamicSharedMemorySize, 4 * TBYTES);
        attr_set = 1;
    }

    float *p_h1, *p_h2, *p_out3;
    int *p_cnt, *p_cur;
    cudaGetSymbolAddress((void**)&p_h1, g_h1);
    cudaGetSymbolAddress((void**)&p_h2, g_h2);
    cudaGetSymbolAddress((void**)&p_out3, g_out3);
    cudaGetSymbolAddress((void**)&p_cnt, g_cnt);
    cudaGetSymbolAddress((void**)&p_cur, g_cur);

    const int gemm_smem = 4 * TBYTES;
    const int gemm_grid = (NN + 127) / 128;          // 782
    const int gath_grid = (NN * 32 + 255) / 256;     // 12500

    // counts -> inv, CSR offsets + placement
    zero_i_kernel<<<(NR + 255) / 256, 256>>>(p_cnt, NR);
    count_kernel<<<(NE + 255) / 256, 256>>>(ei, et);
    inv_kernel<<<(NR + 255) / 256, 256>>>();
    k_blocksum<<<SCAN_NBLK, 256>>>();
    k_scanb<<<1, 32>>>(SCAN_NBLK);
    k_scanlocal<<<SCAN_NBLK, 256>>>();
    zero_i_kernel<<<(NR + 255) / 256, 256>>>(p_cur, NR);
    place_kernel<<<(NE + 255) / 256, 256>>>(ei, et);

    // weight splits
    convert_w_kernel<<<(RR * DD * DD + 255) / 256, 256>>>(W1, 0);
    convert_w_kernel<<<(RR * DD * DD + 255) / 256, 256>>>(W2, 1);

    // layer 1: aggregate raw x, then h1 = tanh(sum_r A_r @ W1_r)
    gather_kernel<<<gath_grid, 256>>>(x);
    gemm_kernel<<<gemm_grid, 256, gemm_smem>>>(0, p_h1);

    // layer 2
    gather_kernel<<<gath_grid, 256>>>(p_h1);
    gemm_kernel<<<gemm_grid, 256, gemm_smem>>>(1, p_h2);

    // layer 3
    transform3_kernel<<<(NN + 31) / 32, 128>>>(p_h2, W3);
    zero_f_kernel<<<(NN * CC + 255) / 256, 256>>>(p_out3, NN * CC);
    scatter3_kernel<<<(NE + 255) / 256, 256>>>(ei, et);

    softmax_kernel<<<(NN + 255) / 256, 256>>>(out, out_size);
}